// round 16
// baseline (speedup 1.0000x reference)
#include <cuda_runtime.h>

#define BN 2
#define NN 512
#define TT 24
#define HH 8
#define DD 8
#define EE 64
#define SCALE 0.125f
#define LOG2E 1.44269504088896340736f

#define GRID_ATTN (BN * TT * HH)          // 384, bids 0..383
#define PRPB 64                           // rows (n-values) per proj CTA
#define GRID_PROJ (BN * TT * (NN / PRPB)) // 384, bids 384..767
#define PXS 68
#define PWS 68
#define NGATE (BN * TT)                   // 48 gates, 8 producers each

typedef unsigned long long u64;

// Intermediate per-head attention output (b, n, t, e), normalized.
__device__ float g_mid[BN * NN * TT * EE];
// Per-(b,t) completion counters (8 attn CTAs each), reset every launch.
__device__ int g_done_bt[NGATE];

__device__ __forceinline__ float fast_exp2(float x) {
    float y;
    asm("ex2.approx.f32 %0, %1;" : "=f"(y) : "f"(x));
    return y;
}
__device__ __forceinline__ u64 pack2(float a, float b) {
    u64 r; asm("mov.b64 %0, {%1, %2};" : "=l"(r) : "f"(a), "f"(b)); return r;
}
__device__ __forceinline__ void unpack2(u64 v, float& a, float& b) {
    asm("mov.b64 {%0, %1}, %2;" : "=f"(a), "=f"(b) : "l"(v));
}
__device__ __forceinline__ u64 fma2(u64 a, u64 b, u64 c) {
    u64 d; asm("fma.rn.f32x2 %0, %1, %2, %3;" : "=l"(d) : "l"(a), "l"(b), "l"(c)); return d;
}
__device__ __forceinline__ u64 add2(u64 a, u64 b) {
    u64 d; asm("add.rn.f32x2 %0, %1, %2;" : "=l"(d) : "l"(a), "l"(b)); return d;
}

__global__ void reset_kernel() {
    int i = threadIdx.x;
    if (i < NGATE) g_done_bt[i] = 0;
}

// SMEM pool: max(attn 2*DD*NN = 8192, proj EE*PWS+EE+PRPB*PXS = 8768 floats).
#define POOL_FLOATS (EE * PWS + EE + PRPB * PXS)

__global__ __launch_bounds__(256, 2) void fused_kernel(
    const float* __restrict__ Vg, const float* __restrict__ Kg, const float* __restrict__ Qg,
    const float* __restrict__ Wv, const float* __restrict__ Wk, const float* __restrict__ Wq,
    const float* __restrict__ Wo, const float* __restrict__ bo, float* __restrict__ out)
{
    __shared__ float pool[POOL_FLOATS];
    __shared__ float sWsmall[3 * DD * DD];

    const int tid = threadIdx.x;

    if (blockIdx.x < GRID_ATTN) {
        // ===================== ATTENTION ROLE (R7 verbatim) =====================
        float* sKT = pool;
        float* sVT = pool + DD * NN;
        float* sWk = sWsmall;
        float* sWv = sWsmall + DD * DD;
        float* sWq = sWsmall + 2 * DD * DD;

        const int gid = blockIdx.x;
        const int h = gid & (HH - 1);
        const int t = (gid >> 3) % TT;
        const int b = gid / (HH * TT);

        if (tid < DD * DD) {
            sWv[tid] = Wv[tid];
            sWk[tid] = Wk[tid];
            sWq[tid] = Wq[tid];
        }
        __syncthreads();

        const size_t base = ((size_t)b * NN * TT + t) * EE + (size_t)h * DD;
        const int rowstride = TT * EE;

        for (int r = tid; r < NN; r += 256) {
            const float4* kp = (const float4*)(Kg + base + (size_t)r * rowstride);
            const float4* vp = (const float4*)(Vg + base + (size_t)r * rowstride);
            float4 ka = kp[0], kb = kp[1];
            float4 va = vp[0], vb = vp[1];
            float kr[8] = {ka.x, ka.y, ka.z, ka.w, kb.x, kb.y, kb.z, kb.w};
            float vr[8] = {va.x, va.y, va.z, va.w, vb.x, vb.y, vb.z, vb.w};
            #pragma unroll
            for (int i = 0; i < DD; i++) {
                float sk = 0.f, sv = 0.f;
                #pragma unroll
                for (int j = 0; j < DD; j++) {
                    sk = fmaf(kr[j], sWk[i * DD + j], sk);
                    sv = fmaf(vr[j], sWv[i * DD + j], sv);
                }
                sKT[i * NN + r] = sk;
                sVT[i * NN + r] = sv;
            }
        }

        u64 qpA[8], qpB[8];
        #pragma unroll
        for (int sel = 0; sel < 2; sel++) {
            const int q = tid + sel * 256;
            const float4* qptr = (const float4*)(Qg + base + (size_t)q * rowstride);
            float4 qa = qptr[0], qb = qptr[1];
            float qr[8] = {qa.x, qa.y, qa.z, qa.w, qb.x, qb.y, qb.z, qb.w};
            #pragma unroll
            for (int i = 0; i < DD; i++) {
                float s = 0.f;
                #pragma unroll
                for (int j = 0; j < DD; j++) s = fmaf(qr[j], sWq[i * DD + j], s);
                s *= (SCALE * LOG2E);
                if (sel == 0) qpA[i] = pack2(s, s); else qpB[i] = pack2(s, s);
            }
        }
        __syncthreads();

        u64 accA[8], accB[8];
        #pragma unroll
        for (int j = 0; j < 8; j++) { accA[j] = 0; accB[j] = 0; }
        u64 lpA = 0, lpB = 0;

        #pragma unroll 2
        for (int k = 0; k < NN; k += 4) {
            u64 sA01 = 0, sA23 = 0, sB01 = 0, sB23 = 0;
            #pragma unroll
            for (int j = 0; j < DD; j++) {
                ulonglong2 kv = *(const ulonglong2*)(sKT + j * NN + k);
                sA01 = fma2(kv.x, qpA[j], sA01);
                sA23 = fma2(kv.y, qpA[j], sA23);
                sB01 = fma2(kv.x, qpB[j], sB01);
                sB23 = fma2(kv.y, qpB[j], sB23);
            }
            float a0, a1, a2, a3, b0, b1, b2, b3;
            unpack2(sA01, a0, a1); unpack2(sA23, a2, a3);
            unpack2(sB01, b0, b1); unpack2(sB23, b2, b3);
            u64 pA01 = pack2(fast_exp2(a0), fast_exp2(a1));
            u64 pA23 = pack2(fast_exp2(a2), fast_exp2(a3));
            u64 pB01 = pack2(fast_exp2(b0), fast_exp2(b1));
            u64 pB23 = pack2(fast_exp2(b2), fast_exp2(b3));
            lpA = add2(lpA, pA01); lpA = add2(lpA, pA23);
            lpB = add2(lpB, pB01); lpB = add2(lpB, pB23);

            #pragma unroll
            for (int j = 0; j < DD; j++) {
                ulonglong2 vv = *(const ulonglong2*)(sVT + j * NN + k);
                accA[j] = fma2(pA01, vv.x, accA[j]);
                accA[j] = fma2(pA23, vv.y, accA[j]);
                accB[j] = fma2(pB01, vv.x, accB[j]);
                accB[j] = fma2(pB23, vv.y, accB[j]);
            }
        }

        #pragma unroll
        for (int sel = 0; sel < 2; sel++) {
            const u64* acc = sel ? accB : accA;
            u64 lp = sel ? lpB : lpA;
            float l0, l1;
            unpack2(lp, l0, l1);
            const float inv = 1.0f / (l0 + l1);
            float o[8];
            #pragma unroll
            for (int j = 0; j < 8; j++) {
                float x, y;
                unpack2(acc[j], x, y);
                o[j] = (x + y) * inv;
            }
            float* op = g_mid + base + (size_t)(tid + sel * 256) * rowstride;
            ((float4*)op)[0] = make_float4(o[0], o[1], o[2], o[3]);
            ((float4*)op)[1] = make_float4(o[4], o[5], o[6], o[7]);
        }

        // Publish: stores -> fence -> barrier -> gate increment.
        __threadfence();
        __syncthreads();
        if (tid == 0) atomicAdd(&g_done_bt[b * TT + t], 1);

    } else {
        // ============ PROJECTION ROLE (R7 loop; per-(b,t) gate, strided rows) ====
        float* sWT = pool;                        // [EE*PWS]
        float* sb  = pool + EE * PWS;             // [EE]
        float* sx  = pool + EE * PWS + EE;        // [PRPB*PXS]

        const int pb = blockIdx.x - GRID_ATTN;    // 0..383
        const int bt = pb >> 3;                   // gate index = b*TT + t
        const int b  = bt / TT;
        const int t  = bt % TT;
        const int n0 = (pb & 7) * PRPB;

        // Stage W and bias BEFORE gating (independent of g_mid).
        for (int idx = tid; idx < EE * EE; idx += 256) {
            int i = idx >> 6, j = idx & 63;
            sWT[j * PWS + i] = Wo[idx];
        }
        if (tid < EE) sb[tid] = bo[tid];

        // Gate: wait for the 8 attn CTAs of this (b,t).
        if (tid == 0) {
            while (atomicAdd(&g_done_bt[bt], 0) < HH)
                __nanosleep(100);
            __threadfence();   // acquire
        }
        __syncthreads();

        // Stage x: 64 rows (n0..n0+63) of 64 floats, row stride TT*EE in g_mid.
        #pragma unroll
        for (int idx = tid * 4; idx < PRPB * EE; idx += 256 * 4) {
            const int i = idx >> 6;
            const int col = idx & 63;
            const size_t goff = (((size_t)b * NN + n0 + i) * TT + t) * EE + col;
            float4 v = *(const float4*)(g_mid + goff);
            float* dst = sx + i * PXS + col;
            dst[0] = v.x; dst[1] = v.y; dst[2] = v.z; dst[3] = v.w;
        }
        __syncthreads();

        const int w = tid >> 5;
        const int lane = tid & 31;
        const int i0 = w * 8;

        u64 aA[4], aB[4];
        {
            u64 b01 = pack2(sb[i0 + 0], sb[i0 + 1]);
            u64 b23 = pack2(sb[i0 + 2], sb[i0 + 3]);
            u64 b45 = pack2(sb[i0 + 4], sb[i0 + 5]);
            u64 b67 = pack2(sb[i0 + 6], sb[i0 + 7]);
            aA[0] = b01; aA[1] = b23; aA[2] = b45; aA[3] = b67;
            aB[0] = b01; aB[1] = b23; aB[2] = b45; aB[3] = b67;
        }

        const float* xA = sx + lane * PXS;
        const float* xB = sx + (lane + 32) * PXS;
        #pragma unroll 4
        for (int j4 = 0; j4 < EE; j4 += 4) {
            float4 xa4 = *(const float4*)(xA + j4);
            float4 xb4 = *(const float4*)(xB + j4);
            const float xa[4] = {xa4.x, xa4.y, xa4.z, xa4.w};
            const float xb[4] = {xb4.x, xb4.y, xb4.z, xb4.w};
            #pragma unroll
            for (int jj = 0; jj < 4; jj++) {
                const ulonglong2* wp = (const ulonglong2*)(sWT + (j4 + jj) * PWS + i0);
                ulonglong2 wa = wp[0];
                ulonglong2 wb = wp[1];
                u64 xpa = pack2(xa[jj], xa[jj]);
                u64 xpb = pack2(xb[jj], xb[jj]);
                aA[0] = fma2(xpa, wa.x, aA[0]);
                aA[1] = fma2(xpa, wa.y, aA[1]);
                aA[2] = fma2(xpa, wb.x, aA[2]);
                aA[3] = fma2(xpa, wb.y, aA[3]);
                aB[0] = fma2(xpb, wa.x, aB[0]);
                aB[1] = fma2(xpb, wa.y, aB[1]);
                aB[2] = fma2(xpb, wb.x, aB[2]);
                aB[3] = fma2(xpb, wb.y, aB[3]);
            }
        }

        __syncthreads();
        #pragma unroll
        for (int r = 0; r < 2; r++) {
            const u64* a = r ? aB : aA;
            float* dst = sx + (lane + r * 32) * PXS + i0;
            #pragma unroll
            for (int c = 0; c < 4; c++) {
                float lo, hi;
                unpack2(a[c], lo, hi);
                dst[2 * c] = lo;
                dst[2 * c + 1] = hi;
            }
        }
        __syncthreads();
        #pragma unroll
        for (int idx = tid * 4; idx < PRPB * EE; idx += 256 * 4) {
            const int i = idx >> 6;
            const int col = idx & 63;
            const float* src = sx + i * PXS + col;
            const size_t goff = (((size_t)b * NN + n0 + i) * TT + t) * EE + col;
            *(float4*)(out + goff) = make_float4(src[0], src[1], src[2], src[3]);
        }
    }
}

extern "C" void kernel_launch(void* const* d_in, const int* in_sizes, int n_in,
                              void* d_out, int out_size)
{
    const float* values = (const float*)d_in[0];
    const float* keys   = (const float*)d_in[1];
    const float* query  = (const float*)d_in[2];
    const float* Wv     = (const float*)d_in[3];
    const float* Wk     = (const float*)d_in[4];
    const float* Wq     = (const float*)d_in[5];
    const float* Wo     = (const float*)d_in[6];
    const float* bo     = (const float*)d_in[7];

    reset_kernel<<<1, 64>>>();
    fused_kernel<<<GRID_ATTN + GRID_PROJ, 256>>>(
        values, keys, query, Wv, Wk, Wq, Wo, bo, (float*)d_out);
}